// round 5
// baseline (speedup 1.0000x reference)
#include <cuda_runtime.h>

// LightGCN 3-layer propagation + batched lookup — Round 5.
// R3 combined-layer structure (proven fastest) + warp-per-node gather:
// 32 lanes = 2 edge slots x 16 float4 columns, unroll 2, shfl reduction.

constexpr int N_USERS = 200000;
constexpr int N_ITEMS = 100000;
constexpr int N_EDGES = 1000000;
constexpr int NT      = N_USERS + N_ITEMS;
constexpr int DV      = 16;                  // 64 floats = 16 float4
constexpr int BATCH   = 8192;

constexpr int NU4 = N_USERS * DV;
constexpr int NI4 = N_ITEMS * DV;

constexpr int SCAN_TPB   = 256;
constexpr int SCAN_ELEMS = 8;
constexpr int SCAN_TILE  = SCAN_TPB * SCAN_ELEMS;
constexpr int NB         = (NT + SCAN_TILE - 1) / SCAN_TILE;

__device__ float4 g_u[3][NU4];
__device__ float4 g_i[3][NI4];
__device__ int    g_cnt[NT];
__device__ int    g_off[NT + 1];
__device__ int    g_cur[NT];
__device__ int    g_bsum[NB];
__device__ int2   g_csr[2 * N_EDGES];        // .x = src node, .y = weight bits

// ---------------- preprocessing ----------------

__global__ void k_zero_cnt() {
    int t = blockIdx.x * blockDim.x + threadIdx.x;
    if (t * 4 < NT) *(int4*)&g_cnt[t * 4] = make_int4(0, 0, 0, 0);
}

__global__ void k_hist(const int* __restrict__ eu, const int* __restrict__ ei) {
    int e = blockIdx.x * blockDim.x + threadIdx.x;
    if (e >= N_EDGES) return;
    atomicAdd(&g_cnt[__ldg(eu + e)], 1);
    atomicAdd(&g_cnt[N_USERS + __ldg(ei + e)], 1);
}

__device__ __forceinline__ int block_exscan(int v, int tid, int* total) {
    __shared__ int wsum[8];
    __shared__ int sh_total;
    int lane = tid & 31, wid = tid >> 5;
    int x = v;
    #pragma unroll
    for (int o = 1; o < 32; o <<= 1) {
        int y = __shfl_up_sync(0xffffffffu, x, o);
        if (lane >= o) x += y;
    }
    if (lane == 31) wsum[wid] = x;
    __syncthreads();
    if (wid == 0) {
        int t8 = (lane < 8) ? wsum[lane] : 0;
        int s = t8;
        #pragma unroll
        for (int o = 1; o < 8; o <<= 1) {
            int y = __shfl_up_sync(0xffffffffu, s, o);
            if (lane >= o) s += y;
        }
        if (lane < 8) wsum[lane] = s - t8;
        if (lane == 7) sh_total = s;
    }
    __syncthreads();
    int excl = wsum[wid] + (x - v);
    *total = sh_total;
    return excl;
}

__global__ void k_scan1() {
    int tid = threadIdx.x;
    int base = blockIdx.x * SCAN_TILE + tid * SCAN_ELEMS;
    int vals[SCAN_ELEMS];
    if (base < NT) {
        int4 a = *(const int4*)&g_cnt[base];
        int4 b = *(const int4*)&g_cnt[base + 4];
        vals[0]=a.x; vals[1]=a.y; vals[2]=a.z; vals[3]=a.w;
        vals[4]=b.x; vals[5]=b.y; vals[6]=b.z; vals[7]=b.w;
    } else {
        #pragma unroll
        for (int k = 0; k < SCAN_ELEMS; k++) vals[k] = 0;
    }
    int tsum = 0;
    #pragma unroll
    for (int k = 0; k < SCAN_ELEMS; k++) tsum += vals[k];
    int total;
    int tbase = block_exscan(tsum, tid, &total);
    if (base < NT) {
        int run = tbase;
        int outv[SCAN_ELEMS];
        #pragma unroll
        for (int k = 0; k < SCAN_ELEMS; k++) { outv[k] = run; run += vals[k]; }
        *(int4*)&g_off[base]     = make_int4(outv[0], outv[1], outv[2], outv[3]);
        *(int4*)&g_off[base + 4] = make_int4(outv[4], outv[5], outv[6], outv[7]);
    }
    if (tid == 0) g_bsum[blockIdx.x] = total;
}

__global__ void k_scan2() {
    int tid = threadIdx.x;
    int v = (tid < NB) ? g_bsum[tid] : 0;
    int total;
    int e = block_exscan(v, tid, &total);
    if (tid < NB) g_bsum[tid] = e;
}

__global__ void k_scan3() {
    int t = blockIdx.x * blockDim.x + threadIdx.x;
    if (t < NT) {
        int v = g_off[t] + g_bsum[t / SCAN_TILE];
        g_off[t] = v;
        g_cur[t] = v;
    }
    if (t == 0) g_off[NT] = 2 * N_EDGES;
}

__global__ void k_permute(const int* __restrict__ eu, const int* __restrict__ ei,
                          const float* __restrict__ nrm) {
    int e = blockIdx.x * blockDim.x + threadIdx.x;
    if (e >= N_EDGES) return;
    int u = __ldg(eu + e);
    int i = __ldg(ei + e);
    int wbits = __float_as_int(__ldg(nrm + e));
    int s1 = atomicAdd(&g_cur[N_USERS + i], 1);
    g_csr[s1] = make_int2(u, wbits);
    int s2 = atomicAdd(&g_cur[u], 1);
    g_csr[s2] = make_int2(i, wbits);
}

// ---------------- propagation layer: warp per node ----------------
// lanes 0-15: even edges, lanes 16-31: odd edges; 16 float4 columns each.

__global__ void k_layer(const float4* __restrict__ uf, const float4* __restrict__ itf,
                        int layer) {
    int gw = (blockIdx.x * blockDim.x + threadIdx.x) >> 5;
    int lane = threadIdx.x & 31;
    if (gw >= NT) return;
    int n = gw;
    int col  = lane & 15;
    int slot = lane >> 4;

    const float4* src;
    float4* dstp;
    if (n < N_USERS) {
        src  = (layer == 0) ? itf : g_i[layer - 1];
        dstp = &g_u[layer][(long long)n * DV];
    } else {
        src  = (layer == 0) ? uf : g_u[layer - 1];
        dstp = &g_i[layer][(long long)(n - N_USERS) * DV];
    }

    int beg = __ldg(&g_off[n]);
    int end = __ldg(&g_off[n + 1]);

    float4 acc0 = make_float4(0.f, 0.f, 0.f, 0.f);
    float4 acc1 = acc0;

    int j = beg + slot;
    // unroll 2: each slot handles edges j and j+2
    for (; j + 2 < end; j += 4) {
        int2 p0 = __ldg(&g_csr[j]);
        int2 p1 = __ldg(&g_csr[j + 2]);
        float w0 = __int_as_float(p0.y);
        float w1 = __int_as_float(p1.y);
        float4 r0 = __ldg(src + (long long)p0.x * DV + col);
        float4 r1 = __ldg(src + (long long)p1.x * DV + col);
        acc0.x += r0.x * w0; acc0.y += r0.y * w0; acc0.z += r0.z * w0; acc0.w += r0.w * w0;
        acc1.x += r1.x * w1; acc1.y += r1.y * w1; acc1.z += r1.z * w1; acc1.w += r1.w * w1;
    }
    if (j < end) {
        int2 p0 = __ldg(&g_csr[j]);
        float w0 = __int_as_float(p0.y);
        float4 r0 = __ldg(src + (long long)p0.x * DV + col);
        acc0.x += r0.x * w0; acc0.y += r0.y * w0; acc0.z += r0.z * w0; acc0.w += r0.w * w0;
    }

    float4 acc = make_float4(acc0.x + acc1.x, acc0.y + acc1.y,
                             acc0.z + acc1.z, acc0.w + acc1.w);
    // combine the two edge slots: lane c += lane c+16
    acc.x += __shfl_down_sync(0xffffffffu, acc.x, 16);
    acc.y += __shfl_down_sync(0xffffffffu, acc.y, 16);
    acc.z += __shfl_down_sync(0xffffffffu, acc.z, 16);
    acc.w += __shfl_down_sync(0xffffffffu, acc.w, 16);

    if (slot == 0) dstp[col] = acc;
}

// ---------------- final batched lookup ----------------

__global__ void k_gather(const float4* __restrict__ uf, const float4* __restrict__ itf,
                         const int* __restrict__ users, const int* __restrict__ pos,
                         const int* __restrict__ neg, float4* __restrict__ out) {
    int t = blockIdx.x * blockDim.x + threadIdx.x;
    const int total = 3 * BATCH * DV;
    if (t >= total) return;
    int sec  = t / (BATCH * DV);
    int rem  = t % (BATCH * DV);
    int r    = rem / DV;
    int lane = rem % DV;

    float4 acc;
    if (sec == 0) {
        int idx = __ldg(users + r) * DV + lane;
        float4 a = uf[idx], b = g_u[0][idx], c = g_u[1][idx], d = g_u[2][idx];
        acc = make_float4(a.x + b.x + c.x + d.x, a.y + b.y + c.y + d.y,
                          a.z + b.z + c.z + d.z, a.w + b.w + c.w + d.w);
    } else {
        int idx = ((sec == 1) ? __ldg(pos + r) : __ldg(neg + r)) * DV + lane;
        float4 a = itf[idx], b = g_i[0][idx], c = g_i[1][idx], d = g_i[2][idx];
        acc = make_float4(a.x + b.x + c.x + d.x, a.y + b.y + c.y + d.y,
                          a.z + b.z + c.z + d.z, a.w + b.w + c.w + d.w);
    }
    const float s = 0.25f;
    out[t] = make_float4(acc.x * s, acc.y * s, acc.z * s, acc.w * s);
}

extern "C" void kernel_launch(void* const* d_in, const int* in_sizes, int n_in,
                              void* d_out, int out_size) {
    const float4* user_feat = (const float4*)d_in[0];
    const float4* item_feat = (const float4*)d_in[1];
    const int*    edge_u    = (const int*)d_in[2];
    const int*    edge_i    = (const int*)d_in[3];
    const float*  nrm       = (const float*)d_in[4];
    const int*    users     = (const int*)d_in[5];
    const int*    pos       = (const int*)d_in[6];
    const int*    neg       = (const int*)d_in[7];
    float4*       out       = (float4*)d_out;

    const int TPB = 256;

    k_zero_cnt<<<(NT / 4 + TPB - 1) / TPB, TPB>>>();
    k_hist<<<(N_EDGES + TPB - 1) / TPB, TPB>>>(edge_u, edge_i);
    k_scan1<<<NB, SCAN_TPB>>>();
    k_scan2<<<1, SCAN_TPB>>>();
    k_scan3<<<(NT + TPB - 1) / TPB, TPB>>>();
    k_permute<<<(N_EDGES + TPB - 1) / TPB, TPB>>>(edge_u, edge_i, nrm);

    const long long lt = (long long)NT * 32;   // one warp per node
    const int layer_blocks = (int)((lt + TPB - 1) / TPB);
    for (int l = 0; l < 3; l++)
        k_layer<<<layer_blocks, TPB>>>(user_feat, item_feat, l);

    const int gt_total = 3 * BATCH * DV;
    k_gather<<<(gt_total + TPB - 1) / TPB, TPB>>>(user_feat, item_feat, users, pos, neg, out);
}

// round 6
// speedup vs baseline: 1.0632x; 1.0632x over previous
#include <cuda_runtime.h>
#include <cuda_fp16.h>

// LightGCN 3-layer propagation + batched lookup — Round 6.
// R3 combined-layer CSR gather (best structure) + fp16 gather sources:
// all accumulation fp32, sources stored as fp16 rows (128B) -> halves
// the dominant gather traffic. CSR stores global source indices.

constexpr int N_USERS = 200000;
constexpr int N_ITEMS = 100000;
constexpr int N_EDGES = 1000000;
constexpr int NT      = N_USERS + N_ITEMS;   // 300,000 nodes (users then items)
constexpr int DV      = 16;                  // 64 floats = 16 float4
constexpr int BATCH   = 8192;

constexpr int SCAN_TPB   = 256;
constexpr int SCAN_ELEMS = 8;
constexpr int SCAN_TILE  = SCAN_TPB * SCAN_ELEMS;
constexpr int NB         = (NT + SCAN_TILE - 1) / SCAN_TILE;

// fp16 source tables, levels 0..2 (rows of 16 x uint2 = 128B)
__device__ uint2  g_src16[3][(long long)NT * 16];
// fp32 layer outputs h1..h3 (rows of 16 x float4 = 256B)
__device__ float4 g_out32[3][(long long)NT * DV];
__device__ int    g_cnt[NT];
__device__ int    g_off[NT + 1];
__device__ int    g_cur[NT];
__device__ int    g_bsum[NB];
__device__ int2   g_csr[2 * N_EDGES];        // .x = GLOBAL src node, .y = weight bits

// ---------------- preprocessing ----------------

__global__ void k_zero_cnt() {
    int t = blockIdx.x * blockDim.x + threadIdx.x;
    if (t * 4 < NT) *(int4*)&g_cnt[t * 4] = make_int4(0, 0, 0, 0);
}

__global__ void k_hist(const int* __restrict__ eu, const int* __restrict__ ei) {
    int e = blockIdx.x * blockDim.x + threadIdx.x;
    if (e >= N_EDGES) return;
    atomicAdd(&g_cnt[__ldg(eu + e)], 1);
    atomicAdd(&g_cnt[N_USERS + __ldg(ei + e)], 1);
}

__device__ __forceinline__ int block_exscan(int v, int tid, int* total) {
    __shared__ int wsum[8];
    __shared__ int sh_total;
    int lane = tid & 31, wid = tid >> 5;
    int x = v;
    #pragma unroll
    for (int o = 1; o < 32; o <<= 1) {
        int y = __shfl_up_sync(0xffffffffu, x, o);
        if (lane >= o) x += y;
    }
    if (lane == 31) wsum[wid] = x;
    __syncthreads();
    if (wid == 0) {
        int t8 = (lane < 8) ? wsum[lane] : 0;
        int s = t8;
        #pragma unroll
        for (int o = 1; o < 8; o <<= 1) {
            int y = __shfl_up_sync(0xffffffffu, s, o);
            if (lane >= o) s += y;
        }
        if (lane < 8) wsum[lane] = s - t8;
        if (lane == 7) sh_total = s;
    }
    __syncthreads();
    int excl = wsum[wid] + (x - v);
    *total = sh_total;
    return excl;
}

__global__ void k_scan1() {
    int tid = threadIdx.x;
    int base = blockIdx.x * SCAN_TILE + tid * SCAN_ELEMS;
    int vals[SCAN_ELEMS];
    if (base < NT) {
        int4 a = *(const int4*)&g_cnt[base];
        int4 b = *(const int4*)&g_cnt[base + 4];
        vals[0]=a.x; vals[1]=a.y; vals[2]=a.z; vals[3]=a.w;
        vals[4]=b.x; vals[5]=b.y; vals[6]=b.z; vals[7]=b.w;
    } else {
        #pragma unroll
        for (int k = 0; k < SCAN_ELEMS; k++) vals[k] = 0;
    }
    int tsum = 0;
    #pragma unroll
    for (int k = 0; k < SCAN_ELEMS; k++) tsum += vals[k];
    int total;
    int tbase = block_exscan(tsum, tid, &total);
    if (base < NT) {
        int run = tbase;
        int outv[SCAN_ELEMS];
        #pragma unroll
        for (int k = 0; k < SCAN_ELEMS; k++) { outv[k] = run; run += vals[k]; }
        *(int4*)&g_off[base]     = make_int4(outv[0], outv[1], outv[2], outv[3]);
        *(int4*)&g_off[base + 4] = make_int4(outv[4], outv[5], outv[6], outv[7]);
    }
    if (tid == 0) g_bsum[blockIdx.x] = total;
}

__global__ void k_scan2() {
    int tid = threadIdx.x;
    int v = (tid < NB) ? g_bsum[tid] : 0;
    int total;
    int e = block_exscan(v, tid, &total);
    if (tid < NB) g_bsum[tid] = e;
}

__global__ void k_scan3() {
    int t = blockIdx.x * blockDim.x + threadIdx.x;
    if (t < NT) {
        int v = g_off[t] + g_bsum[t / SCAN_TILE];
        g_off[t] = v;
        g_cur[t] = v;
    }
    if (t == 0) g_off[NT] = 2 * N_EDGES;
}

__global__ void k_permute(const int* __restrict__ eu, const int* __restrict__ ei,
                          const float* __restrict__ nrm) {
    int e = blockIdx.x * blockDim.x + threadIdx.x;
    if (e >= N_EDGES) return;
    int u = __ldg(eu + e);
    int i = __ldg(ei + e);
    int wbits = __float_as_int(__ldg(nrm + e));
    int s1 = atomicAdd(&g_cur[N_USERS + i], 1);   // item dst <- src user (global = u)
    g_csr[s1] = make_int2(u, wbits);
    int s2 = atomicAdd(&g_cur[u], 1);             // user dst <- src item (global = N_USERS+i)
    g_csr[s2] = make_int2(N_USERS + i, wbits);
}

// ---------------- fp16 conversion of input tables (level 0 sources) -----------

__global__ void k_convert(const float4* __restrict__ uf, const float4* __restrict__ itf) {
    long long t = (long long)blockIdx.x * blockDim.x + threadIdx.x;
    if (t >= (long long)NT * 16) return;
    long long n = t >> 4;
    int c = (int)(t & 15);
    float4 v = (n < N_USERS) ? __ldg(uf + n * DV + c)
                             : __ldg(itf + (n - N_USERS) * DV + c);
    __half2 h01 = __float22half2_rn(make_float2(v.x, v.y));
    __half2 h23 = __float22half2_rn(make_float2(v.z, v.w));
    uint2 p;
    p.x = *reinterpret_cast<unsigned*>(&h01);
    p.y = *reinterpret_cast<unsigned*>(&h23);
    g_src16[0][t] = p;
}

// ---------------- propagation layer (combined, fp16 sources) ----------------
// 16 lanes per node; each lane = 4 feature columns; unroll 4 edges.

__device__ __forceinline__ void fma4(float4& acc, uint2 s, float w) {
    __half2 h01 = *reinterpret_cast<__half2*>(&s.x);
    __half2 h23 = *reinterpret_cast<__half2*>(&s.y);
    float2 f01 = __half22float2(h01);
    float2 f23 = __half22float2(h23);
    acc.x += f01.x * w; acc.y += f01.y * w;
    acc.z += f23.x * w; acc.w += f23.y * w;
}

__global__ void k_layer(int layer) {
    long long t = (long long)blockIdx.x * blockDim.x + threadIdx.x;
    int n = (int)(t >> 4);
    int col = (int)(t & 15);
    if (n >= NT) return;

    const uint2* __restrict__ src = g_src16[layer];

    int beg = __ldg(&g_off[n]);
    int end = __ldg(&g_off[n + 1]);

    float4 a0 = make_float4(0.f,0.f,0.f,0.f), a1 = a0, a2 = a0, a3 = a0;

    int j = beg;
    for (; j + 3 < end; j += 4) {
        int2 p0 = __ldg(&g_csr[j]);
        int2 p1 = __ldg(&g_csr[j + 1]);
        int2 p2 = __ldg(&g_csr[j + 2]);
        int2 p3 = __ldg(&g_csr[j + 3]);
        uint2 s0 = __ldg(src + (long long)p0.x * 16 + col);
        uint2 s1 = __ldg(src + (long long)p1.x * 16 + col);
        uint2 s2 = __ldg(src + (long long)p2.x * 16 + col);
        uint2 s3 = __ldg(src + (long long)p3.x * 16 + col);
        fma4(a0, s0, __int_as_float(p0.y));
        fma4(a1, s1, __int_as_float(p1.y));
        fma4(a2, s2, __int_as_float(p2.y));
        fma4(a3, s3, __int_as_float(p3.y));
    }
    for (; j < end; j++) {
        int2 p0 = __ldg(&g_csr[j]);
        uint2 s0 = __ldg(src + (long long)p0.x * 16 + col);
        fma4(a0, s0, __int_as_float(p0.y));
    }

    float4 acc = make_float4(a0.x + a1.x + a2.x + a3.x,
                             a0.y + a1.y + a2.y + a3.y,
                             a0.z + a1.z + a2.z + a3.z,
                             a0.w + a1.w + a2.w + a3.w);

    g_out32[layer][t] = acc;
    if (layer < 2) {
        __half2 h01 = __float22half2_rn(make_float2(acc.x, acc.y));
        __half2 h23 = __float22half2_rn(make_float2(acc.z, acc.w));
        uint2 p;
        p.x = *reinterpret_cast<unsigned*>(&h01);
        p.y = *reinterpret_cast<unsigned*>(&h23);
        g_src16[layer + 1][t] = p;
    }
}

// ---------------- final batched lookup ----------------

__global__ void k_gather(const float4* __restrict__ uf, const float4* __restrict__ itf,
                         const int* __restrict__ users, const int* __restrict__ pos,
                         const int* __restrict__ neg, float4* __restrict__ out) {
    int t = blockIdx.x * blockDim.x + threadIdx.x;
    const int total = 3 * BATCH * DV;
    if (t >= total) return;
    int sec  = t / (BATCH * DV);
    int rem  = t % (BATCH * DV);
    int r    = rem / DV;
    int lane = rem % DV;

    float4 a;
    long long gi;
    if (sec == 0) {
        int idx = __ldg(users + r);
        a  = __ldg(uf + (long long)idx * DV + lane);
        gi = (long long)idx * DV + lane;
    } else {
        int idx = (sec == 1) ? __ldg(pos + r) : __ldg(neg + r);
        a  = __ldg(itf + (long long)idx * DV + lane);
        gi = (long long)(N_USERS + idx) * DV + lane;
    }
    float4 b = g_out32[0][gi];
    float4 c = g_out32[1][gi];
    float4 d = g_out32[2][gi];

    const float s = 0.25f;
    out[t] = make_float4((a.x + b.x + c.x + d.x) * s,
                         (a.y + b.y + c.y + d.y) * s,
                         (a.z + b.z + c.z + d.z) * s,
                         (a.w + b.w + c.w + d.w) * s);
}

extern "C" void kernel_launch(void* const* d_in, const int* in_sizes, int n_in,
                              void* d_out, int out_size) {
    const float4* user_feat = (const float4*)d_in[0];
    const float4* item_feat = (const float4*)d_in[1];
    const int*    edge_u    = (const int*)d_in[2];
    const int*    edge_i    = (const int*)d_in[3];
    const float*  nrm       = (const float*)d_in[4];
    const int*    users     = (const int*)d_in[5];
    const int*    pos       = (const int*)d_in[6];
    const int*    neg       = (const int*)d_in[7];
    float4*       out       = (float4*)d_out;

    const int TPB = 256;

    k_zero_cnt<<<(NT / 4 + TPB - 1) / TPB, TPB>>>();
    k_hist<<<(N_EDGES + TPB - 1) / TPB, TPB>>>(edge_u, edge_i);
    k_scan1<<<NB, SCAN_TPB>>>();
    k_scan2<<<1, SCAN_TPB>>>();
    k_scan3<<<(NT + TPB - 1) / TPB, TPB>>>();
    k_permute<<<(N_EDGES + TPB - 1) / TPB, TPB>>>(edge_u, edge_i, nrm);

    const long long ct = (long long)NT * 16;
    k_convert<<<(int)((ct + TPB - 1) / TPB), TPB>>>(user_feat, item_feat);

    const long long lt = (long long)NT * 16;
    const int layer_blocks = (int)((lt + TPB - 1) / TPB);
    for (int l = 0; l < 3; l++)
        k_layer<<<layer_blocks, TPB>>>(l);

    const int gt_total = 3 * BATCH * DV;
    k_gather<<<(gt_total + TPB - 1) / TPB, TPB>>>(user_feat, item_feat, users, pos, neg, out);
}

// round 7
// speedup vs baseline: 1.1494x; 1.0811x over previous
#include <cuda_runtime.h>
#include <cuda_fp16.h>

// LightGCN 3-layer propagation + batched lookup — Round 7.
// R3 layer-kernel shape EXACTLY (16 lanes/node, unroll 2, tail<=1),
// only change: fp16 gather sources (8B/lane), fp32 accumulation/outputs.

constexpr int N_USERS = 200000;
constexpr int N_ITEMS = 100000;
constexpr int N_EDGES = 1000000;
constexpr int NT      = N_USERS + N_ITEMS;   // users then items
constexpr int DV      = 16;                  // 64 floats = 16 float4
constexpr int BATCH   = 8192;

constexpr int SCAN_TPB   = 256;
constexpr int SCAN_ELEMS = 8;
constexpr int SCAN_TILE  = SCAN_TPB * SCAN_ELEMS;
constexpr int NB         = (NT + SCAN_TILE - 1) / SCAN_TILE;

// fp16 source tables (levels 0..2), rows = 16 x uint2 = 128B
__device__ uint2  g_src16[3][(long long)NT * 16];
// fp32 layer outputs h1..h3, rows = 16 x float4 = 256B
__device__ float4 g_out32[3][(long long)NT * 16];
__device__ int    g_cnt[NT];
__device__ int    g_off[NT + 1];
__device__ int    g_cur[NT];
__device__ int    g_bsum[NB];
__device__ int2   g_csr[2 * N_EDGES];        // .x = GLOBAL src node, .y = weight bits

// ---------------- preprocessing ----------------

__global__ void k_zero_cnt() {
    int t = blockIdx.x * blockDim.x + threadIdx.x;
    if (t * 4 < NT) *(int4*)&g_cnt[t * 4] = make_int4(0, 0, 0, 0);
}

__global__ void k_hist(const int* __restrict__ eu, const int* __restrict__ ei) {
    int e = blockIdx.x * blockDim.x + threadIdx.x;
    if (e >= N_EDGES) return;
    atomicAdd(&g_cnt[__ldg(eu + e)], 1);
    atomicAdd(&g_cnt[N_USERS + __ldg(ei + e)], 1);
}

__device__ __forceinline__ int block_exscan(int v, int tid, int* total) {
    __shared__ int wsum[8];
    __shared__ int sh_total;
    int lane = tid & 31, wid = tid >> 5;
    int x = v;
    #pragma unroll
    for (int o = 1; o < 32; o <<= 1) {
        int y = __shfl_up_sync(0xffffffffu, x, o);
        if (lane >= o) x += y;
    }
    if (lane == 31) wsum[wid] = x;
    __syncthreads();
    if (wid == 0) {
        int t8 = (lane < 8) ? wsum[lane] : 0;
        int s = t8;
        #pragma unroll
        for (int o = 1; o < 8; o <<= 1) {
            int y = __shfl_up_sync(0xffffffffu, s, o);
            if (lane >= o) s += y;
        }
        if (lane < 8) wsum[lane] = s - t8;
        if (lane == 7) sh_total = s;
    }
    __syncthreads();
    int excl = wsum[wid] + (x - v);
    *total = sh_total;
    return excl;
}

__global__ void k_scan1() {
    int tid = threadIdx.x;
    int base = blockIdx.x * SCAN_TILE + tid * SCAN_ELEMS;
    int vals[SCAN_ELEMS];
    if (base < NT) {
        int4 a = *(const int4*)&g_cnt[base];
        int4 b = *(const int4*)&g_cnt[base + 4];
        vals[0]=a.x; vals[1]=a.y; vals[2]=a.z; vals[3]=a.w;
        vals[4]=b.x; vals[5]=b.y; vals[6]=b.z; vals[7]=b.w;
    } else {
        #pragma unroll
        for (int k = 0; k < SCAN_ELEMS; k++) vals[k] = 0;
    }
    int tsum = 0;
    #pragma unroll
    for (int k = 0; k < SCAN_ELEMS; k++) tsum += vals[k];
    int total;
    int tbase = block_exscan(tsum, tid, &total);
    if (base < NT) {
        int run = tbase;
        int outv[SCAN_ELEMS];
        #pragma unroll
        for (int k = 0; k < SCAN_ELEMS; k++) { outv[k] = run; run += vals[k]; }
        *(int4*)&g_off[base]     = make_int4(outv[0], outv[1], outv[2], outv[3]);
        *(int4*)&g_off[base + 4] = make_int4(outv[4], outv[5], outv[6], outv[7]);
    }
    if (tid == 0) g_bsum[blockIdx.x] = total;
}

__global__ void k_scan2() {
    int tid = threadIdx.x;
    int v = (tid < NB) ? g_bsum[tid] : 0;
    int total;
    int e = block_exscan(v, tid, &total);
    if (tid < NB) g_bsum[tid] = e;
}

__global__ void k_scan3() {
    int t = blockIdx.x * blockDim.x + threadIdx.x;
    if (t < NT) {
        int v = g_off[t] + g_bsum[t / SCAN_TILE];
        g_off[t] = v;
        g_cur[t] = v;
    }
    if (t == 0) g_off[NT] = 2 * N_EDGES;
}

__global__ void k_permute(const int* __restrict__ eu, const int* __restrict__ ei,
                          const float* __restrict__ nrm) {
    int e = blockIdx.x * blockDim.x + threadIdx.x;
    if (e >= N_EDGES) return;
    int u = __ldg(eu + e);
    int i = __ldg(ei + e);
    int wbits = __float_as_int(__ldg(nrm + e));
    int s1 = atomicAdd(&g_cur[N_USERS + i], 1);   // item dst <- src user (global u)
    g_csr[s1] = make_int2(u, wbits);
    int s2 = atomicAdd(&g_cur[u], 1);             // user dst <- src item (global N_USERS+i)
    g_csr[s2] = make_int2(N_USERS + i, wbits);
}

// ---------------- fp16 conversion of input tables (level-0 sources) ----------

__global__ void k_convert(const float4* __restrict__ uf, const float4* __restrict__ itf) {
    long long t = (long long)blockIdx.x * blockDim.x + threadIdx.x;
    if (t >= (long long)NT * 16) return;
    long long n = t >> 4;
    int c = (int)(t & 15);
    float4 v = (n < N_USERS) ? __ldg(uf + n * DV + c)
                             : __ldg(itf + (n - N_USERS) * DV + c);
    __half2 h01 = __float22half2_rn(make_float2(v.x, v.y));
    __half2 h23 = __float22half2_rn(make_float2(v.z, v.w));
    uint2 p;
    p.x = *reinterpret_cast<unsigned*>(&h01);
    p.y = *reinterpret_cast<unsigned*>(&h23);
    g_src16[0][t] = p;
}

// ---------------- propagation layer: R3 shape, fp16 sources ----------------

__device__ __forceinline__ void fma4(float4& acc, uint2 s, float w) {
    __half2 h01 = *reinterpret_cast<__half2*>(&s.x);
    __half2 h23 = *reinterpret_cast<__half2*>(&s.y);
    float2 f01 = __half22float2(h01);
    float2 f23 = __half22float2(h23);
    acc.x += f01.x * w; acc.y += f01.y * w;
    acc.z += f23.x * w; acc.w += f23.y * w;
}

__global__ void k_layer(int layer) {
    long long t = (long long)blockIdx.x * blockDim.x + threadIdx.x;
    int n = (int)(t >> 4);
    int lane = (int)(t & 15);
    if (n >= NT) return;

    const uint2* __restrict__ src = g_src16[layer];

    int beg = __ldg(&g_off[n]);
    int end = __ldg(&g_off[n + 1]);

    float4 acc0 = make_float4(0.f, 0.f, 0.f, 0.f);
    float4 acc1 = acc0;
    int j = beg;
    for (; j + 1 < end; j += 2) {
        int2 p0 = __ldg(&g_csr[j]);
        int2 p1 = __ldg(&g_csr[j + 1]);
        uint2 s0 = __ldg(src + (long long)p0.x * 16 + lane);
        uint2 s1 = __ldg(src + (long long)p1.x * 16 + lane);
        fma4(acc0, s0, __int_as_float(p0.y));
        fma4(acc1, s1, __int_as_float(p1.y));
    }
    if (j < end) {
        int2 p0 = __ldg(&g_csr[j]);
        uint2 s0 = __ldg(src + (long long)p0.x * 16 + lane);
        fma4(acc0, s0, __int_as_float(p0.y));
    }

    float4 acc = make_float4(acc0.x + acc1.x, acc0.y + acc1.y,
                             acc0.z + acc1.z, acc0.w + acc1.w);

    g_out32[layer][t] = acc;
    if (layer < 2) {
        __half2 h01 = __float22half2_rn(make_float2(acc.x, acc.y));
        __half2 h23 = __float22half2_rn(make_float2(acc.z, acc.w));
        uint2 p;
        p.x = *reinterpret_cast<unsigned*>(&h01);
        p.y = *reinterpret_cast<unsigned*>(&h23);
        g_src16[layer + 1][t] = p;
    }
}

// ---------------- final batched lookup ----------------

__global__ void k_gather(const float4* __restrict__ uf, const float4* __restrict__ itf,
                         const int* __restrict__ users, const int* __restrict__ pos,
                         const int* __restrict__ neg, float4* __restrict__ out) {
    int t = blockIdx.x * blockDim.x + threadIdx.x;
    const int total = 3 * BATCH * DV;
    if (t >= total) return;
    int sec  = t / (BATCH * DV);
    int rem  = t % (BATCH * DV);
    int r    = rem / DV;
    int lane = rem % DV;

    float4 a;
    long long gi;
    if (sec == 0) {
        int idx = __ldg(users + r);
        a  = __ldg(uf + (long long)idx * DV + lane);
        gi = (long long)idx * DV + lane;
    } else {
        int idx = (sec == 1) ? __ldg(pos + r) : __ldg(neg + r);
        a  = __ldg(itf + (long long)idx * DV + lane);
        gi = (long long)(N_USERS + idx) * DV + lane;
    }
    float4 b = g_out32[0][gi];
    float4 c = g_out32[1][gi];
    float4 d = g_out32[2][gi];

    const float s = 0.25f;
    out[t] = make_float4((a.x + b.x + c.x + d.x) * s,
                         (a.y + b.y + c.y + d.y) * s,
                         (a.z + b.z + c.z + d.z) * s,
                         (a.w + b.w + c.w + d.w) * s);
}

extern "C" void kernel_launch(void* const* d_in, const int* in_sizes, int n_in,
                              void* d_out, int out_size) {
    const float4* user_feat = (const float4*)d_in[0];
    const float4* item_feat = (const float4*)d_in[1];
    const int*    edge_u    = (const int*)d_in[2];
    const int*    edge_i    = (const int*)d_in[3];
    const float*  nrm       = (const float*)d_in[4];
    const int*    users     = (const int*)d_in[5];
    const int*    pos       = (const int*)d_in[6];
    const int*    neg       = (const int*)d_in[7];
    float4*       out       = (float4*)d_out;

    const int TPB = 256;

    k_zero_cnt<<<(NT / 4 + TPB - 1) / TPB, TPB>>>();
    k_hist<<<(N_EDGES + TPB - 1) / TPB, TPB>>>(edge_u, edge_i);
    k_scan1<<<NB, SCAN_TPB>>>();
    k_scan2<<<1, SCAN_TPB>>>();
    k_scan3<<<(NT + TPB - 1) / TPB, TPB>>>();
    k_permute<<<(N_EDGES + TPB - 1) / TPB, TPB>>>(edge_u, edge_i, nrm);

    const long long ct = (long long)NT * 16;
    k_convert<<<(int)((ct + TPB - 1) / TPB), TPB>>>(user_feat, item_feat);

    const int layer_blocks = (int)((ct + TPB - 1) / TPB);
    for (int l = 0; l < 3; l++)
        k_layer<<<layer_blocks, TPB>>>(l);

    const int gt_total = 3 * BATCH * DV;
    k_gather<<<(gt_total + TPB - 1) / TPB, TPB>>>(user_feat, item_feat, users, pos, neg, out);
}

// round 8
// speedup vs baseline: 1.1976x; 1.0419x over previous
#include <cuda_runtime.h>

// LightGCN 3-layer propagation + batched lookup — Round 8.
// R3 (best, 293us) verbatim with ONE change: streaming cache hints in k_layer
// (__ldcs for CSR, __stcs for layer outputs) so the 77MB source table stays
// L2-resident instead of being evicted by the write stream.

constexpr int N_USERS = 200000;
constexpr int N_ITEMS = 100000;
constexpr int N_EDGES = 1000000;
constexpr int NT      = N_USERS + N_ITEMS;   // 300,000 destination nodes
constexpr int DV      = 16;                  // 64 floats = 16 float4
constexpr int BATCH   = 8192;

constexpr int NU4 = N_USERS * DV;
constexpr int NI4 = N_ITEMS * DV;

constexpr int SCAN_TPB   = 256;
constexpr int SCAN_ELEMS = 8;
constexpr int SCAN_TILE  = SCAN_TPB * SCAN_ELEMS;
constexpr int NB         = (NT + SCAN_TILE - 1) / SCAN_TILE;

__device__ float4 g_u[3][NU4];
__device__ float4 g_i[3][NI4];
__device__ int    g_cnt[NT];
__device__ int    g_off[NT + 1];
__device__ int    g_cur[NT];
__device__ int    g_bsum[NB];
__device__ int2   g_csr[2 * N_EDGES];        // .x = src node (local), .y = weight bits

// ---------------- preprocessing ----------------

__global__ void k_zero_cnt() {
    int t = blockIdx.x * blockDim.x + threadIdx.x;
    if (t * 4 < NT) *(int4*)&g_cnt[t * 4] = make_int4(0, 0, 0, 0);
}

__global__ void k_hist(const int* __restrict__ eu, const int* __restrict__ ei) {
    int e = blockIdx.x * blockDim.x + threadIdx.x;
    if (e >= N_EDGES) return;
    atomicAdd(&g_cnt[__ldg(eu + e)], 1);
    atomicAdd(&g_cnt[N_USERS + __ldg(ei + e)], 1);
}

__device__ __forceinline__ int block_exscan(int v, int tid, int* total) {
    __shared__ int wsum[8];
    __shared__ int sh_total;
    int lane = tid & 31, wid = tid >> 5;
    int x = v;
    #pragma unroll
    for (int o = 1; o < 32; o <<= 1) {
        int y = __shfl_up_sync(0xffffffffu, x, o);
        if (lane >= o) x += y;
    }
    if (lane == 31) wsum[wid] = x;
    __syncthreads();
    if (wid == 0) {
        int t8 = (lane < 8) ? wsum[lane] : 0;
        int s = t8;
        #pragma unroll
        for (int o = 1; o < 8; o <<= 1) {
            int y = __shfl_up_sync(0xffffffffu, s, o);
            if (lane >= o) s += y;
        }
        if (lane < 8) wsum[lane] = s - t8;
        if (lane == 7) sh_total = s;
    }
    __syncthreads();
    int excl = wsum[wid] + (x - v);
    *total = sh_total;
    return excl;
}

__global__ void k_scan1() {
    int tid = threadIdx.x;
    int base = blockIdx.x * SCAN_TILE + tid * SCAN_ELEMS;
    int vals[SCAN_ELEMS];
    if (base < NT) {
        int4 a = *(const int4*)&g_cnt[base];
        int4 b = *(const int4*)&g_cnt[base + 4];
        vals[0]=a.x; vals[1]=a.y; vals[2]=a.z; vals[3]=a.w;
        vals[4]=b.x; vals[5]=b.y; vals[6]=b.z; vals[7]=b.w;
    } else {
        #pragma unroll
        for (int k = 0; k < SCAN_ELEMS; k++) vals[k] = 0;
    }
    int tsum = 0;
    #pragma unroll
    for (int k = 0; k < SCAN_ELEMS; k++) tsum += vals[k];
    int total;
    int tbase = block_exscan(tsum, tid, &total);
    if (base < NT) {
        int run = tbase;
        int outv[SCAN_ELEMS];
        #pragma unroll
        for (int k = 0; k < SCAN_ELEMS; k++) { outv[k] = run; run += vals[k]; }
        *(int4*)&g_off[base]     = make_int4(outv[0], outv[1], outv[2], outv[3]);
        *(int4*)&g_off[base + 4] = make_int4(outv[4], outv[5], outv[6], outv[7]);
    }
    if (tid == 0) g_bsum[blockIdx.x] = total;
}

__global__ void k_scan2() {
    int tid = threadIdx.x;
    int v = (tid < NB) ? g_bsum[tid] : 0;
    int total;
    int e = block_exscan(v, tid, &total);
    if (tid < NB) g_bsum[tid] = e;
}

__global__ void k_scan3() {
    int t = blockIdx.x * blockDim.x + threadIdx.x;
    if (t < NT) {
        int v = g_off[t] + g_bsum[t / SCAN_TILE];
        g_off[t] = v;
        g_cur[t] = v;
    }
    if (t == 0) g_off[NT] = 2 * N_EDGES;
}

__global__ void k_permute(const int* __restrict__ eu, const int* __restrict__ ei,
                          const float* __restrict__ nrm) {
    int e = blockIdx.x * blockDim.x + threadIdx.x;
    if (e >= N_EDGES) return;
    int u = __ldg(eu + e);
    int i = __ldg(ei + e);
    int wbits = __float_as_int(__ldg(nrm + e));
    int s1 = atomicAdd(&g_cur[N_USERS + i], 1);   // item dst <- user src
    g_csr[s1] = make_int2(u, wbits);
    int s2 = atomicAdd(&g_cur[u], 1);             // user dst <- item src
    g_csr[s2] = make_int2(i, wbits);
}

// ---------------- propagation layer (gather, no atomics) ----------------
// 16 lanes/node, unroll 2 — R3 shape. Streaming hints on CSR + outputs.

__global__ void k_layer(const float4* __restrict__ uf, const float4* __restrict__ itf,
                        int layer) {
    int t = blockIdx.x * blockDim.x + threadIdx.x;
    int n = t >> 4;
    int lane = t & 15;
    if (n >= NT) return;

    const float4* srcU = (layer == 0) ? uf  : g_u[layer - 1];
    const float4* srcI = (layer == 0) ? itf : g_i[layer - 1];
    const float4* src;
    float4* dst;
    if (n < N_USERS) { src = srcI; dst = &g_u[layer][n * DV + lane]; }
    else             { src = srcU; dst = &g_i[layer][(n - N_USERS) * DV + lane]; }

    int beg = __ldg(&g_off[n]);
    int end = __ldg(&g_off[n + 1]);

    float4 acc0 = make_float4(0.f, 0.f, 0.f, 0.f);
    float4 acc1 = make_float4(0.f, 0.f, 0.f, 0.f);
    int j = beg;
    for (; j + 1 < end; j += 2) {
        int2 p0 = __ldcs(&g_csr[j]);
        int2 p1 = __ldcs(&g_csr[j + 1]);
        float w0 = __int_as_float(p0.y);
        float w1 = __int_as_float(p1.y);
        float4 r0 = __ldg(&src[p0.x * DV + lane]);
        float4 r1 = __ldg(&src[p1.x * DV + lane]);
        acc0.x += r0.x * w0; acc0.y += r0.y * w0; acc0.z += r0.z * w0; acc0.w += r0.w * w0;
        acc1.x += r1.x * w1; acc1.y += r1.y * w1; acc1.z += r1.z * w1; acc1.w += r1.w * w1;
    }
    if (j < end) {
        int2 p0 = __ldcs(&g_csr[j]);
        float w0 = __int_as_float(p0.y);
        float4 r0 = __ldg(&src[p0.x * DV + lane]);
        acc0.x += r0.x * w0; acc0.y += r0.y * w0; acc0.z += r0.z * w0; acc0.w += r0.w * w0;
    }
    float4 res = make_float4(acc0.x + acc1.x, acc0.y + acc1.y,
                             acc0.z + acc1.z, acc0.w + acc1.w);
    __stcs(dst, res);   // evict-first: don't displace the source table in L2
}

// ---------------- final batched lookup ----------------

__global__ void k_gather(const float4* __restrict__ uf, const float4* __restrict__ itf,
                         const int* __restrict__ users, const int* __restrict__ pos,
                         const int* __restrict__ neg, float4* __restrict__ out) {
    int t = blockIdx.x * blockDim.x + threadIdx.x;
    const int total = 3 * BATCH * DV;
    if (t >= total) return;
    int sec  = t / (BATCH * DV);
    int rem  = t % (BATCH * DV);
    int r    = rem / DV;
    int lane = rem % DV;

    float4 acc;
    if (sec == 0) {
        int idx = __ldg(users + r) * DV + lane;
        float4 a = uf[idx], b = g_u[0][idx], c = g_u[1][idx], d = g_u[2][idx];
        acc = make_float4(a.x + b.x + c.x + d.x, a.y + b.y + c.y + d.y,
                          a.z + b.z + c.z + d.z, a.w + b.w + c.w + d.w);
    } else {
        int idx = ((sec == 1) ? __ldg(pos + r) : __ldg(neg + r)) * DV + lane;
        float4 a = itf[idx], b = g_i[0][idx], c = g_i[1][idx], d = g_i[2][idx];
        acc = make_float4(a.x + b.x + c.x + d.x, a.y + b.y + c.y + d.y,
                          a.z + b.z + c.z + d.z, a.w + b.w + c.w + d.w);
    }
    const float s = 0.25f;
    out[t] = make_float4(acc.x * s, acc.y * s, acc.z * s, acc.w * s);
}

extern "C" void kernel_launch(void* const* d_in, const int* in_sizes, int n_in,
                              void* d_out, int out_size) {
    const float4* user_feat = (const float4*)d_in[0];
    const float4* item_feat = (const float4*)d_in[1];
    const int*    edge_u    = (const int*)d_in[2];
    const int*    edge_i    = (const int*)d_in[3];
    const float*  nrm       = (const float*)d_in[4];
    const int*    users     = (const int*)d_in[5];
    const int*    pos       = (const int*)d_in[6];
    const int*    neg       = (const int*)d_in[7];
    float4*       out       = (float4*)d_out;

    const int TPB = 256;

    k_zero_cnt<<<(NT / 4 + TPB - 1) / TPB, TPB>>>();
    k_hist<<<(N_EDGES + TPB - 1) / TPB, TPB>>>(edge_u, edge_i);
    k_scan1<<<NB, SCAN_TPB>>>();
    k_scan2<<<1, SCAN_TPB>>>();
    k_scan3<<<(NT + TPB - 1) / TPB, TPB>>>();
    k_permute<<<(N_EDGES + TPB - 1) / TPB, TPB>>>(edge_u, edge_i, nrm);

    const long long lt = (long long)NT * DV;
    const int layer_blocks = (int)((lt + TPB - 1) / TPB);
    for (int l = 0; l < 3; l++)
        k_layer<<<layer_blocks, TPB>>>(user_feat, item_feat, l);

    const int gt_total = 3 * BATCH * DV;
    k_gather<<<(gt_total + TPB - 1) / TPB, TPB>>>(user_feat, item_feat, users, pos, neg, out);
}

// round 9
// speedup vs baseline: 1.2795x; 1.0684x over previous
#include <cuda_runtime.h>

// LightGCN 3-layer propagation + batched lookup — Round 9.
// R3 (best, 293us) with ONE change in k_layer: CSR entries are loaded
// cooperatively (16 coalesced entries per node-group) and distributed by
// shuffle, removing the per-lane broadcast CSR load (L1-wavefront bound fix).

constexpr int N_USERS = 200000;
constexpr int N_ITEMS = 100000;
constexpr int N_EDGES = 1000000;
constexpr int NT      = N_USERS + N_ITEMS;   // 300,000 destination nodes
constexpr int DV      = 16;                  // 64 floats = 16 float4
constexpr int BATCH   = 8192;

constexpr int NU4 = N_USERS * DV;
constexpr int NI4 = N_ITEMS * DV;

constexpr int SCAN_TPB   = 256;
constexpr int SCAN_ELEMS = 8;
constexpr int SCAN_TILE  = SCAN_TPB * SCAN_ELEMS;
constexpr int NB         = (NT + SCAN_TILE - 1) / SCAN_TILE;

__device__ float4 g_u[3][NU4];
__device__ float4 g_i[3][NI4];
__device__ int    g_cnt[NT];
__device__ int    g_off[NT + 1];
__device__ int    g_cur[NT];
__device__ int    g_bsum[NB];
__device__ int2   g_csr[2 * N_EDGES];        // .x = src node (local), .y = weight bits

// ---------------- preprocessing ----------------

__global__ void k_zero_cnt() {
    int t = blockIdx.x * blockDim.x + threadIdx.x;
    if (t * 4 < NT) *(int4*)&g_cnt[t * 4] = make_int4(0, 0, 0, 0);
}

__global__ void k_hist(const int* __restrict__ eu, const int* __restrict__ ei) {
    int e = blockIdx.x * blockDim.x + threadIdx.x;
    if (e >= N_EDGES) return;
    atomicAdd(&g_cnt[__ldg(eu + e)], 1);
    atomicAdd(&g_cnt[N_USERS + __ldg(ei + e)], 1);
}

__device__ __forceinline__ int block_exscan(int v, int tid, int* total) {
    __shared__ int wsum[8];
    __shared__ int sh_total;
    int lane = tid & 31, wid = tid >> 5;
    int x = v;
    #pragma unroll
    for (int o = 1; o < 32; o <<= 1) {
        int y = __shfl_up_sync(0xffffffffu, x, o);
        if (lane >= o) x += y;
    }
    if (lane == 31) wsum[wid] = x;
    __syncthreads();
    if (wid == 0) {
        int t8 = (lane < 8) ? wsum[lane] : 0;
        int s = t8;
        #pragma unroll
        for (int o = 1; o < 8; o <<= 1) {
            int y = __shfl_up_sync(0xffffffffu, s, o);
            if (lane >= o) s += y;
        }
        if (lane < 8) wsum[lane] = s - t8;
        if (lane == 7) sh_total = s;
    }
    __syncthreads();
    int excl = wsum[wid] + (x - v);
    *total = sh_total;
    return excl;
}

__global__ void k_scan1() {
    int tid = threadIdx.x;
    int base = blockIdx.x * SCAN_TILE + tid * SCAN_ELEMS;
    int vals[SCAN_ELEMS];
    if (base < NT) {
        int4 a = *(const int4*)&g_cnt[base];
        int4 b = *(const int4*)&g_cnt[base + 4];
        vals[0]=a.x; vals[1]=a.y; vals[2]=a.z; vals[3]=a.w;
        vals[4]=b.x; vals[5]=b.y; vals[6]=b.z; vals[7]=b.w;
    } else {
        #pragma unroll
        for (int k = 0; k < SCAN_ELEMS; k++) vals[k] = 0;
    }
    int tsum = 0;
    #pragma unroll
    for (int k = 0; k < SCAN_ELEMS; k++) tsum += vals[k];
    int total;
    int tbase = block_exscan(tsum, tid, &total);
    if (base < NT) {
        int run = tbase;
        int outv[SCAN_ELEMS];
        #pragma unroll
        for (int k = 0; k < SCAN_ELEMS; k++) { outv[k] = run; run += vals[k]; }
        *(int4*)&g_off[base]     = make_int4(outv[0], outv[1], outv[2], outv[3]);
        *(int4*)&g_off[base + 4] = make_int4(outv[4], outv[5], outv[6], outv[7]);
    }
    if (tid == 0) g_bsum[blockIdx.x] = total;
}

__global__ void k_scan2() {
    int tid = threadIdx.x;
    int v = (tid < NB) ? g_bsum[tid] : 0;
    int total;
    int e = block_exscan(v, tid, &total);
    if (tid < NB) g_bsum[tid] = e;
}

__global__ void k_scan3() {
    int t = blockIdx.x * blockDim.x + threadIdx.x;
    if (t < NT) {
        int v = g_off[t] + g_bsum[t / SCAN_TILE];
        g_off[t] = v;
        g_cur[t] = v;
    }
    if (t == 0) g_off[NT] = 2 * N_EDGES;
}

__global__ void k_permute(const int* __restrict__ eu, const int* __restrict__ ei,
                          const float* __restrict__ nrm) {
    int e = blockIdx.x * blockDim.x + threadIdx.x;
    if (e >= N_EDGES) return;
    int u = __ldg(eu + e);
    int i = __ldg(ei + e);
    int wbits = __float_as_int(__ldg(nrm + e));
    int s1 = atomicAdd(&g_cur[N_USERS + i], 1);   // item dst <- user src
    g_csr[s1] = make_int2(u, wbits);
    int s2 = atomicAdd(&g_cur[u], 1);             // user dst <- item src
    g_csr[s2] = make_int2(i, wbits);
}

// ---------------- propagation layer: cooperative CSR + shuffle ----------------
// 16 lanes per node. Lanes jointly load up to 16 CSR entries (coalesced),
// then iterate edges distributing (src, w) via shfl; 1 row load per edge.

__global__ void k_layer(const float4* __restrict__ uf, const float4* __restrict__ itf,
                        int layer) {
    int t = blockIdx.x * blockDim.x + threadIdx.x;
    int n = t >> 4;
    int lane = t & 15;
    if (n >= NT) return;   // never taken: grid exactly covers NT*16

    const float4* srcU = (layer == 0) ? uf  : g_u[layer - 1];
    const float4* srcI = (layer == 0) ? itf : g_i[layer - 1];
    const float4* src;
    float4* dst;
    if (n < N_USERS) { src = srcI; dst = &g_u[layer][n * DV + lane]; }
    else             { src = srcU; dst = &g_i[layer][(n - N_USERS) * DV + lane]; }

    int beg = __ldg(&g_off[n]);
    int end = __ldg(&g_off[n + 1]);

    float4 acc0 = make_float4(0.f, 0.f, 0.f, 0.f);
    float4 acc1 = acc0;

    for (int base = beg; base < end; base += 16) {
        int k = base + lane;
        int2 p = (k < end) ? __ldg(&g_csr[k]) : make_int2(0, 0);
        int cnt = end - base;
        if (cnt > 16) cnt = 16;

        int m = 0;
        for (; m + 1 < cnt; m += 2) {
            int   s0 = __shfl_sync(0xffffffffu, p.x, m,     16);
            int   w0b= __shfl_sync(0xffffffffu, p.y, m,     16);
            int   s1 = __shfl_sync(0xffffffffu, p.x, m + 1, 16);
            int   w1b= __shfl_sync(0xffffffffu, p.y, m + 1, 16);
            float4 r0 = __ldg(&src[s0 * DV + lane]);
            float4 r1 = __ldg(&src[s1 * DV + lane]);
            float w0 = __int_as_float(w0b);
            float w1 = __int_as_float(w1b);
            acc0.x += r0.x * w0; acc0.y += r0.y * w0; acc0.z += r0.z * w0; acc0.w += r0.w * w0;
            acc1.x += r1.x * w1; acc1.y += r1.y * w1; acc1.z += r1.z * w1; acc1.w += r1.w * w1;
        }
        if (m < cnt) {
            int   s0 = __shfl_sync(0xffffffffu, p.x, m, 16);
            int   w0b= __shfl_sync(0xffffffffu, p.y, m, 16);
            float4 r0 = __ldg(&src[s0 * DV + lane]);
            float w0 = __int_as_float(w0b);
            acc0.x += r0.x * w0; acc0.y += r0.y * w0; acc0.z += r0.z * w0; acc0.w += r0.w * w0;
        }
    }

    *dst = make_float4(acc0.x + acc1.x, acc0.y + acc1.y,
                       acc0.z + acc1.z, acc0.w + acc1.w);
}

// ---------------- final batched lookup ----------------

__global__ void k_gather(const float4* __restrict__ uf, const float4* __restrict__ itf,
                         const int* __restrict__ users, const int* __restrict__ pos,
                         const int* __restrict__ neg, float4* __restrict__ out) {
    int t = blockIdx.x * blockDim.x + threadIdx.x;
    const int total = 3 * BATCH * DV;
    if (t >= total) return;
    int sec  = t / (BATCH * DV);
    int rem  = t % (BATCH * DV);
    int r    = rem / DV;
    int lane = rem % DV;

    float4 acc;
    if (sec == 0) {
        int idx = __ldg(users + r) * DV + lane;
        float4 a = uf[idx], b = g_u[0][idx], c = g_u[1][idx], d = g_u[2][idx];
        acc = make_float4(a.x + b.x + c.x + d.x, a.y + b.y + c.y + d.y,
                          a.z + b.z + c.z + d.z, a.w + b.w + c.w + d.w);
    } else {
        int idx = ((sec == 1) ? __ldg(pos + r) : __ldg(neg + r)) * DV + lane;
        float4 a = itf[idx], b = g_i[0][idx], c = g_i[1][idx], d = g_i[2][idx];
        acc = make_float4(a.x + b.x + c.x + d.x, a.y + b.y + c.y + d.y,
                          a.z + b.z + c.z + d.z, a.w + b.w + c.w + d.w);
    }
    const float s = 0.25f;
    out[t] = make_float4(acc.x * s, acc.y * s, acc.z * s, acc.w * s);
}

extern "C" void kernel_launch(void* const* d_in, const int* in_sizes, int n_in,
                              void* d_out, int out_size) {
    const float4* user_feat = (const float4*)d_in[0];
    const float4* item_feat = (const float4*)d_in[1];
    const int*    edge_u    = (const int*)d_in[2];
    const int*    edge_i    = (const int*)d_in[3];
    const float*  nrm       = (const float*)d_in[4];
    const int*    users     = (const int*)d_in[5];
    const int*    pos       = (const int*)d_in[6];
    const int*    neg       = (const int*)d_in[7];
    float4*       out       = (float4*)d_out;

    const int TPB = 256;

    k_zero_cnt<<<(NT / 4 + TPB - 1) / TPB, TPB>>>();
    k_hist<<<(N_EDGES + TPB - 1) / TPB, TPB>>>(edge_u, edge_i);
    k_scan1<<<NB, SCAN_TPB>>>();
    k_scan2<<<1, SCAN_TPB>>>();
    k_scan3<<<(NT + TPB - 1) / TPB, TPB>>>();
    k_permute<<<(N_EDGES + TPB - 1) / TPB, TPB>>>(edge_u, edge_i, nrm);

    const long long lt = (long long)NT * DV;
    const int layer_blocks = (int)((lt + TPB - 1) / TPB);
    for (int l = 0; l < 3; l++)
        k_layer<<<layer_blocks, TPB>>>(user_feat, item_feat, l);

    const int gt_total = 3 * BATCH * DV;
    k_gather<<<(gt_total + TPB - 1) / TPB, TPB>>>(user_feat, item_feat, users, pos, neg, out);
}